// round 16
// baseline (speedup 1.0000x reference)
#include <cuda_runtime.h>
#include <math.h>

#define SEQ   2048
#define NH    16
#define HD    64
#define DM    1024
#define BATCH 2
#define ROWS  (BATCH*SEQ)      // 4096

// ---------------- scratch (device globals; no allocations allowed) ----------
__device__ __align__(128) float g_x [ROWS*DM];           // tf32-rounded x
__device__ __align__(128) float g_w [4*DM*DM];           // tf32-rounded wq,wk,wv,wo
__device__ __align__(128) float g_q [BATCH*NH*SEQ*HD];   // [b][h][s][d] tf32 bits, *log2e/8
__device__ __align__(128) float g_k [BATCH*NH*SEQ*HD];   // [b][h][s][d] tf32 bits
__device__ __align__(128) float g_v [BATCH*NH*SEQ*HD];   // [b][h][d][s] TRANSPOSED tf32 bits
__device__ __align__(128) float g_ao[ROWS*DM];           // [b*S+s][h*64+d], tf32 bits
__device__ __align__(128) float g_cos[SEQ*(HD/2)];
__device__ __align__(128) float g_sin[SEQ*(HD/2)];

// ---------------- small PTX helpers -----------------------------------------
__device__ __forceinline__ unsigned f2tf(float x){
    unsigned u; asm("cvt.rna.tf32.f32 %0, %1;" : "=r"(u) : "f"(x)); return u;
}
__device__ __forceinline__ float tfbits(float x){ return __uint_as_float(f2tf(x)); }
__device__ __forceinline__ float ex2(float x){
    float y; asm("ex2.approx.f32 %0, %1;" : "=f"(y) : "f"(x)); return y;
}
__device__ __forceinline__ void mma_tf32(float* c, const unsigned* a, const unsigned* b){
    asm volatile(
        "mma.sync.aligned.m16n8k8.row.col.f32.tf32.tf32.f32 "
        "{%0,%1,%2,%3},{%4,%5,%6,%7},{%8,%9},{%0,%1,%2,%3};\n"
        : "+f"(c[0]), "+f"(c[1]), "+f"(c[2]), "+f"(c[3])
        : "r"(a[0]), "r"(a[1]), "r"(a[2]), "r"(a[3]), "r"(b[0]), "r"(b[1]));
}
__device__ __forceinline__ void cp16(float* s, const float* g){
    unsigned sa = (unsigned)__cvta_generic_to_shared(s);
    asm volatile("cp.async.cg.shared.global [%0], [%1], 16;\n" :: "r"(sa), "l"(g));
}
__device__ __forceinline__ void cpcommit(){ asm volatile("cp.async.commit_group;\n" ::: "memory"); }
template<int N> __device__ __forceinline__ void cpwait(){
    asm volatile("cp.async.wait_group %0;\n" :: "n"(N) : "memory");
}

// ---------------- input pre-conversion to tf32 (done once per launch) -------
__global__ void cvt_inputs_kernel(const float4* __restrict__ x,
                                  const float4* __restrict__ w0,
                                  const float4* __restrict__ w1,
                                  const float4* __restrict__ w2,
                                  const float4* __restrict__ w3)
{
    const int NX = ROWS*DM/4;   // 1048576 float4
    const int NW = DM*DM/4;     // 262144 float4
    int i = blockIdx.x*blockDim.x + threadIdx.x;   // 0 .. NX+4*NW-1
    float4 v; float4* dst;
    if (i < NX){ v = x[i]; dst = ((float4*)g_x) + i; }
    else {
        int j = i - NX; int w = j / NW; int o = j - w*NW;
        const float4* src = (w==0)?w0:(w==1)?w1:(w==2)?w2:w3;
        v = src[o]; dst = ((float4*)g_w) + (size_t)w*NW + o;
    }
    v.x = tfbits(v.x); v.y = tfbits(v.y); v.z = tfbits(v.z); v.w = tfbits(v.w);
    *dst = v;
}

// ---------------- RoPE cos/sin table (fp64 for accuracy) --------------------
__global__ void rope_table_kernel(){
    int idx = blockIdx.x*blockDim.x + threadIdx.x;   // SEQ*32 entries
    if (idx < SEQ*(HD/2)){
        int s = idx >> 5, i = idx & 31;
        double freq = pow(10000.0, -(double)(2*i)/64.0);
        double ang  = (double)s * freq;
        g_cos[idx] = (float)cos(ang);
        g_sin[idx] = (float)sin(ang);
    }
}

// ---------------- tiled TF32 GEMM v2: 256x128 block, 512 thr, 3-stage -------
// Block tile 256x128 (B-blocks re-read x16 instead of x32: -25% L2 traffic).
// 16 warps (8m x 2n), warp tile 32x64 — per-warp inner code unchanged.
// 3-stage cp.async ring with ONE sync/iter: load for kt+2 targets stage
// (kt+2)%3 == (kt-1)%3, whose readers finished before the top-of-loop sync.
// k-slot remap + LDS.64 pairs as before; SAS=40 conflict-free.
#define BK   32
#define SAS  40
#define ASTG (256*SAS)            // A floats per stage
#define BSTG (128*SAS)            // B floats per stage
#define GSMEM ((3*ASTG + 3*BSTG)*4)   // 184320 bytes

template<int MODE>
__global__ __launch_bounds__(512,1)
void gemm_kernel(float* __restrict__ C)
{
    extern __shared__ float sm[];
    float* sA = sm;                // 3 stages of ASTG
    float* sB = sm + 3*ASTG;       // 3 stages of BSTG

    const int tid = threadIdx.x, lane = tid & 31, warp = tid >> 5;
    const int wm = warp & 7, wn = warp >> 3;          // 8x2 warp grid, 32x64 warp tile
    const int bm = blockIdx.y, bn = blockIdx.x;
    const int lr = lane >> 2, lc = lane & 3;

    int sel = 0, nb = bn;
    if (MODE == 1){ sel = bn >> 3; nb = bn & 7; }
    const float* Ag = ((MODE == 0) ? g_ao : g_x) + (size_t)bm*256*DM;
    const float* Bg = g_w + (size_t)((MODE==1)? sel : 3)*DM*DM + (size_t)nb*128*DM;

    float acc[2][8][4];
    #pragma unroll
    for (int i=0;i<2;i++)
        #pragma unroll
        for (int j=0;j<8;j++)
            #pragma unroll
            for (int k=0;k<4;k++) acc[i][j][k]=0.f;

    // per stage: A 256x32 (2048 cp16) + B 128x32 (1024 cp16) = 6 per thread
    auto load_tile = [&](int kt, int st){
        const int k0 = kt*BK;
        float* a_s = sA + st*ASTG;
        float* b_s = sB + st*BSTG;
        #pragma unroll
        for (int i=0;i<6;i++){
            int ch = tid + i*512;
            if (ch < 2048){
                int row = ch >> 3, seg = ch & 7;
                cp16(&a_s[row*SAS + seg*4], Ag + (size_t)row*DM + k0 + seg*4);
            } else {
                int cb = ch - 2048;
                int row = cb >> 3, seg = cb & 7;
                cp16(&b_s[row*SAS + seg*4], Bg + (size_t)row*DM + k0 + seg*4);
            }
        }
        cpcommit();
    };

    const int NT = DM/BK;   // 32
    load_tile(0, 0);
    load_tile(1, 1);

    int st = 0;
    for (int kt = 0; kt < NT; ++kt){
        if (kt < NT-1) cpwait<1>(); else cpwait<0>();
        __syncthreads();                       // stage st holds tile kt; all
                                               // readers of stage (kt-1)%3 done
        if (kt+2 < NT){
            int st2 = st+2; if (st2 >= 3) st2 -= 3;
            load_tile(kt+2, st2);
        }
        const float* a_s = sA + st*ASTG;
        const float* b_s = sB + st*BSTG;

        #pragma unroll
        for (int kk=0; kk<4; ++kk){
            const int ko = kk*8;
            unsigned af[2][4], bf[8][2];
            #pragma unroll
            for (int mt=0; mt<2; ++mt){
                int r = wm*32 + mt*16 + lr;
                float2 a0 = *(const float2*)&a_s[ r   *SAS + ko + 2*lc];
                float2 a1 = *(const float2*)&a_s[(r+8)*SAS + ko + 2*lc];
                af[mt][0] = __float_as_uint(a0.x);
                af[mt][1] = __float_as_uint(a1.x);
                af[mt][2] = __float_as_uint(a0.y);
                af[mt][3] = __float_as_uint(a1.y);
            }
            #pragma unroll
            for (int nf=0; nf<8; ++nf){
                int nr = wn*64 + nf*8 + lr;
                float2 b0 = *(const float2*)&b_s[nr*SAS + ko + 2*lc];
                bf[nf][0] = __float_as_uint(b0.x);
                bf[nf][1] = __float_as_uint(b0.y);
            }
            #pragma unroll
            for (int mt=0; mt<2; ++mt)
                #pragma unroll
                for (int nf=0; nf<8; ++nf)
                    mma_tf32(acc[mt][nf], af[mt], bf[nf]);
        }
        if (++st >= 3) st = 0;
    }

    // ---- epilogue (C-frag layout independent of k-remap) ----
    #pragma unroll
    for (int mt=0; mt<2; ++mt){
        const int row = bm*256 + wm*32 + mt*16 + lr;
        #pragma unroll
        for (int nf=0; nf<8; ++nf){
            float c0 = acc[mt][nf][0], c1 = acc[mt][nf][1];
            float c2 = acc[mt][nf][2], c3 = acc[mt][nf][3];
            const int jl = nb*128 + wn*64 + nf*8 + 2*lc;   // column within matrix
            if (MODE == 0){
                C[(size_t)row*DM + jl]       = c0;
                C[(size_t)row*DM + jl + 1]   = c1;
                C[(size_t)(row+8)*DM + jl]   = c2;
                C[(size_t)(row+8)*DM + jl+1] = c3;
            } else {
                const int h = jl >> 6, d = jl & 63;
                const int b = row >> 11, s = row & (SEQ-1);
                if (sel < 2){
                    float* dst = (sel==0) ? g_q : g_k;
                    const size_t base = ((size_t)(b*NH + h)*SEQ + s)*HD + d;
                    const int ti  = s*(HD/2) + (d>>1);
                    const int ti2 = ti + 8*(HD/2);
                    float cs  = g_cos[ti],  sn  = g_sin[ti];
                    float cs2 = g_cos[ti2], sn2 = g_sin[ti2];
                    // q pre-scale: 1/sqrt(64) * log2(e)  (softmax runs in base 2)
                    const float qs = (sel==0) ? 0.125f*1.4426950408889634f : 1.0f;
                    dst[base]          = tfbits(qs*(c0*cs  - c1*sn));
                    dst[base+1]        = tfbits(qs*(c0*sn  + c1*cs));
                    dst[base+8*HD]     = tfbits(qs*(c2*cs2 - c3*sn2));
                    dst[base+8*HD+1]   = tfbits(qs*(c2*sn2 + c3*cs2));
                } else {
                    // V stored TRANSPOSED: [b][h][d][s]
                    float* dst = g_v;
                    const size_t tb = ((size_t)(b*NH + h)*HD);
                    dst[(tb + d  )*SEQ + s  ] = tfbits(c0);
                    dst[(tb + d+1)*SEQ + s  ] = tfbits(c1);
                    dst[(tb + d  )*SEQ + s+8] = tfbits(c2);
                    dst[(tb + d+1)*SEQ + s+8] = tfbits(c3);
                }
            }
        }
    }
}

// ---------------- FlashAttention v8 (unchanged from R15 best) ----------------
#define KS 72    // Q/K smem row stride: 8B-bank conflict-free LDS.64 pairs
#define VS 72    // V^T smem row stride: 8B-bank conflict-free LDS.64 pairs
#define ATTN_SMEM ((128*KS + 2*64*KS + 2*64*VS)*4)   // 110592 bytes

__global__ __launch_bounds__(128)
void attn_kernel()
{
    extern __shared__ float sm[];
    float* sQ = sm;                 // 128*KS
    float* sK = sQ + 128*KS;        // 2 stages of 64*KS
    float* sV = sK + 2*64*KS;       // 2 stages of 64*VS (transposed: row = d)

    const int tid = threadIdx.x, lane = tid & 31, warp = tid >> 5;
    const int lr = lane >> 2, lc = lane & 3;
    const int qt = blockIdx.x, bh = blockIdx.y;

    const float* qp = g_q + ((size_t)bh*SEQ + qt*128)*HD;
    const float* kp = g_k + (size_t)bh*SEQ*HD;
    const float* vp = g_v + (size_t)bh*HD*SEQ;     // transposed base

    auto load_kv = [&](int t, int buf){
        const float* kt_ = kp + (size_t)t*64*HD;
        const float* vt_ = vp + t*64;              // column offset in [d][s]
        #pragma unroll
        for (int c=0;c<8;c++){                 // 64 rows x 16 float4 / 128 thr
            int ch = tid + c*128;
            int row = ch >> 4, vec = ch & 15;
            cp16(&sK[buf*64*KS + row*KS + vec*4], kt_ + row*HD + vec*4);
            cp16(&sV[buf*64*VS + row*VS + vec*4], vt_ + (size_t)row*SEQ + vec*4);
        }
    };

    load_kv(0, 0); cpcommit();

    // Q tile (128 rows) -> smem (tf32 bits, pre-scaled by log2e/sqrt(64))
    #pragma unroll
    for (int c=0;c<16;c++){
        int ch = tid + c*128;
        int row = ch >> 4, vec = ch & 15;
        *(float4*)(&sQ[row*KS + vec*4]) = *(const float4*)(qp + (size_t)row*HD + vec*4);
    }
    __syncthreads();

    // Q fragments register-resident (reused all 32 tiles; paired LDS.64)
    unsigned qa[2][8][4];
    #pragma unroll
    for (int mt=0; mt<2; ++mt){
        const int r = warp*32 + mt*16 + lr;
        #pragma unroll
        for (int ks=0; ks<8; ++ks){
            float2 q0 = *(const float2*)&sQ[ r   *KS + ks*8 + 2*lc];
            float2 q1 = *(const float2*)&sQ[(r+8)*KS + ks*8 + 2*lc];
            qa[mt][ks][0] = __float_as_uint(q0.x);
            qa[mt][ks][1] = __float_as_uint(q1.x);
            qa[mt][ks][2] = __float_as_uint(q0.y);
            qa[mt][ks][3] = __float_as_uint(q1.y);
        }
    }

    float o[2][8][4];
    #pragma unroll
    for (int mt=0; mt<2; ++mt)
        #pragma unroll
        for (int i=0;i<8;i++)
            #pragma unroll
            for (int j=0;j<4;j++) o[mt][i][j]=0.f;
    float lp[2][2];                           // per-thread partial row sums
    #pragma unroll
    for (int mt=0; mt<2; ++mt){ lp[mt][0]=0.f; lp[mt][1]=0.f; }

    for (int t=0; t<SEQ/64; ++t){
        const int buf = t & 1;
        if (t+1 < SEQ/64){ load_kv(t+1, buf^1); cpcommit(); cpwait<1>(); }
        else             { cpwait<0>(); }
        __syncthreads();

        const float* kb = &sK[buf*64*KS];
        const float* vb = &sV[buf*64*VS];

        float sc[2][8][4];
        #pragma unroll
        for (int mt=0; mt<2; ++mt)
            #pragma unroll
            for (int i=0;i<8;i++)
                #pragma unroll
                for (int j=0;j<4;j++) sc[mt][i][j]=0.f;

        // PV for score group f: ex2 -> truncate -> row-sum -> 16 mmas.
        auto pv_group = [&](int f){
            unsigned pa[2][4];
            #pragma unroll
            for (int mt=0; mt<2; ++mt){
                unsigned u0 = __float_as_uint(ex2(sc[mt][f][0])) & 0xffffe000u;
                unsigned u1 = __float_as_uint(ex2(sc[mt][f][1])) & 0xffffe000u;
                unsigned u2 = __float_as_uint(ex2(sc[mt][f][2])) & 0xffffe000u;
                unsigned u3 = __float_as_uint(ex2(sc[mt][f][3])) & 0xffffe000u;
                lp[mt][0] += __uint_as_float(u0) + __uint_as_float(u1);
                lp[mt][1] += __uint_as_float(u2) + __uint_as_float(u3);
                pa[mt][0] = u0;  pa[mt][1] = u2;   // slot lc   -> col 2lc
                pa[mt][2] = u1;  pa[mt][3] = u3;   // slot lc+4 -> col 2lc+1
            }
            #pragma unroll
            for (int nf=0; nf<8; ++nf){
                float2 vv = *(const float2*)&vb[(nf*8+lr)*VS + f*8 + 2*lc];
                unsigned bb[2];
                bb[0] = __float_as_uint(vv.x);
                bb[1] = __float_as_uint(vv.y);
                mma_tf32(o[0][nf], pa[0], bb);
                mma_tf32(o[1][nf], pa[1], bb);
            }
        };

        // Interleaved mainloop: QK group nf, then PV of group nf-2.
        #pragma unroll
        for (int nf=0; nf<8; ++nf){
            const int krow = (nf*8 + lr)*KS;
            #pragma unroll
            for (int ks=0; ks<8; ++ks){
                float2 kv2 = *(const float2*)&kb[krow + ks*8 + 2*lc];
                unsigned bb[2];
                bb[0] = __float_as_uint(kv2.x);
                bb[1] = __float_as_uint(kv2.y);
                mma_tf32(sc[0][nf], qa[0][ks], bb);
                mma_tf32(sc[1][nf], qa[1][ks], bb);
            }
            if (nf >= 2) pv_group(nf-2);
        }
        pv_group(6);
        pv_group(7);

        __syncthreads();   // all warps done with buf before it is refilled
    }

    // epilogue: single quad-reduction of row sums, normalize, write out
    const int b = bh >> 4, h = bh & 15;
    #pragma unroll
    for (int mt=0; mt<2; ++mt){
        float sA_ = lp[mt][0], sB_ = lp[mt][1];
        sA_ += __shfl_xor_sync(0xffffffffu, sA_, 1);
        sA_ += __shfl_xor_sync(0xffffffffu, sA_, 2);
        sB_ += __shfl_xor_sync(0xffffffffu, sB_, 1);
        sB_ += __shfl_xor_sync(0xffffffffu, sB_, 2);
        const float iA = 1.f/sA_, iB = 1.f/sB_;
        const int srow = qt*128 + warp*32 + mt*16 + lr;
        float* aoA = g_ao + (size_t)(b*SEQ + srow)*DM + h*HD;
        float* aoB = aoA + 8*DM;
        #pragma unroll
        for (int nf=0; nf<8; ++nf){
            const int d = nf*8 + 2*lc;
            aoA[d]   = tfbits(o[mt][nf][0]*iA);  aoA[d+1] = tfbits(o[mt][nf][1]*iA);
            aoB[d]   = tfbits(o[mt][nf][2]*iB);  aoB[d+1] = tfbits(o[mt][nf][3]*iB);
        }
    }
}

// ---------------- launch -----------------------------------------------------
extern "C" void kernel_launch(void* const* d_in, const int* in_sizes, int n_in,
                              void* d_out, int out_size)
{
    const float4* x  = (const float4*)d_in[0];
    const float4* wq = (const float4*)d_in[1];
    const float4* wk = (const float4*)d_in[2];
    const float4* wv = (const float4*)d_in[3];
    const float4* wo = (const float4*)d_in[4];
    float* out = (float*)d_out;

    static int attr_done = 0;
    if (!attr_done){
        cudaFuncSetAttribute(gemm_kernel<1>, cudaFuncAttributeMaxDynamicSharedMemorySize, GSMEM);
        cudaFuncSetAttribute(gemm_kernel<0>, cudaFuncAttributeMaxDynamicSharedMemorySize, GSMEM);
        cudaFuncSetAttribute(attn_kernel,    cudaFuncAttributeMaxDynamicSharedMemorySize, ATTN_SMEM);
        attr_done = 1;
    }

    // pre-convert x and all weights to tf32 bit-patterns
    cvt_inputs_kernel<<<(ROWS*DM/4 + 4*DM*DM/4)/256, 256>>>(x, wq, wk, wv, wo);

    rope_table_kernel<<<(SEQ*(HD/2) + 255)/256, 256>>>();

    // QKV projection + RoPE (V stored transposed):  grid = (24 n, 16 m of 256)
    gemm_kernel<1><<<dim3(24, 16), 512, GSMEM>>>(nullptr);

    // FlashAttention: (16 q-tiles of 128 rows, 32 batch*heads)
    attn_kernel<<<dim3(SEQ/128, BATCH*NH), 128, ATTN_SMEM>>>();

    // Output projection: grid = (8 n, 16 m of 256)
    gemm_kernel<0><<<dim3(8, 16), 512, GSMEM>>>(out);
}

// round 17
// speedup vs baseline: 1.0033x; 1.0033x over previous
#include <cuda_runtime.h>
#include <math.h>

#define SEQ   2048
#define NH    16
#define HD    64
#define DM    1024
#define BATCH 2
#define ROWS  (BATCH*SEQ)      // 4096

// ---------------- scratch (device globals; no allocations allowed) ----------
__device__ __align__(128) float g_x [ROWS*DM];           // tf32-rounded x
__device__ __align__(128) float g_w [4*DM*DM];           // tf32-rounded wq,wk,wv,wo
__device__ __align__(128) float g_q [BATCH*NH*SEQ*HD];   // [b][h][s][d] tf32 bits, *log2e/8
__device__ __align__(128) float g_k [BATCH*NH*SEQ*HD];   // [b][h][s][d] tf32 bits
__device__ __align__(128) float g_v [BATCH*NH*SEQ*HD];   // [b][h][d][s] TRANSPOSED tf32 bits
__device__ __align__(128) float g_ao[ROWS*DM];           // [b*S+s][h*64+d], tf32 bits
__device__ __align__(128) float g_cos[SEQ*(HD/2)];
__device__ __align__(128) float g_sin[SEQ*(HD/2)];

// ---------------- small PTX helpers -----------------------------------------
__device__ __forceinline__ unsigned f2tf(float x){
    unsigned u; asm("cvt.rna.tf32.f32 %0, %1;" : "=r"(u) : "f"(x)); return u;
}
__device__ __forceinline__ float tfbits(float x){ return __uint_as_float(f2tf(x)); }
__device__ __forceinline__ float ex2(float x){
    float y; asm("ex2.approx.f32 %0, %1;" : "=f"(y) : "f"(x)); return y;
}
__device__ __forceinline__ void mma_tf32(float* c, const unsigned* a, const unsigned* b){
    asm volatile(
        "mma.sync.aligned.m16n8k8.row.col.f32.tf32.tf32.f32 "
        "{%0,%1,%2,%3},{%4,%5,%6,%7},{%8,%9},{%0,%1,%2,%3};\n"
        : "+f"(c[0]), "+f"(c[1]), "+f"(c[2]), "+f"(c[3])
        : "r"(a[0]), "r"(a[1]), "r"(a[2]), "r"(a[3]), "r"(b[0]), "r"(b[1]));
}
__device__ __forceinline__ void cp16(float* s, const float* g){
    unsigned sa = (unsigned)__cvta_generic_to_shared(s);
    asm volatile("cp.async.cg.shared.global [%0], [%1], 16;\n" :: "r"(sa), "l"(g));
}
__device__ __forceinline__ void cpcommit(){ asm volatile("cp.async.commit_group;\n" ::: "memory"); }
template<int N> __device__ __forceinline__ void cpwait(){
    asm volatile("cp.async.wait_group %0;\n" :: "n"(N) : "memory");
}

// ---------------- input pre-conversion to tf32 (done once per launch) -------
__global__ void cvt_inputs_kernel(const float4* __restrict__ x,
                                  const float4* __restrict__ w0,
                                  const float4* __restrict__ w1,
                                  const float4* __restrict__ w2,
                                  const float4* __restrict__ w3)
{
    const int NX = ROWS*DM/4;   // 1048576 float4
    const int NW = DM*DM/4;     // 262144 float4
    int i = blockIdx.x*blockDim.x + threadIdx.x;   // 0 .. NX+4*NW-1
    float4 v; float4* dst;
    if (i < NX){ v = x[i]; dst = ((float4*)g_x) + i; }
    else {
        int j = i - NX; int w = j / NW; int o = j - w*NW;
        const float4* src = (w==0)?w0:(w==1)?w1:(w==2)?w2:w3;
        v = src[o]; dst = ((float4*)g_w) + (size_t)w*NW + o;
    }
    v.x = tfbits(v.x); v.y = tfbits(v.y); v.z = tfbits(v.z); v.w = tfbits(v.w);
    *dst = v;
}

// ---------------- RoPE cos/sin table (fp64 for accuracy) --------------------
__global__ void rope_table_kernel(){
    int idx = blockIdx.x*blockDim.x + threadIdx.x;   // SEQ*32 entries
    if (idx < SEQ*(HD/2)){
        int s = idx >> 5, i = idx & 31;
        double freq = pow(10000.0, -(double)(2*i)/64.0);
        double ang  = (double)s * freq;
        g_cos[idx] = (float)cos(ang);
        g_sin[idx] = (float)sin(ang);
    }
}

// ---------------- tiled TF32 GEMM (reverted to R11/R15 proven version) ------
// k-slot remap: mma slot lc -> col ko+2lc, slot lc+4 -> col ko+2lc+1.
// A/B fragment loads become adjacent pairs -> LDS.64 (half the LDS count).
// SAS=40: conflict-free LDS.64 per half-warp. 2-stage, 2 CTAs/SM.
#define BK   32
#define SAS  40
#define GST  (128*SAS)            // floats per stage per matrix
#define GSMEM (2*2*GST*4)         // 81920 bytes (2-stage)

template<int MODE>
__global__ __launch_bounds__(256,2)
void gemm_kernel(float* __restrict__ C)
{
    extern __shared__ float sm[];
    float* sA = sm;                // 2 stages
    float* sB = sm + 2*GST;

    const int tid = threadIdx.x, lane = tid & 31, warp = tid >> 5;
    const int wm = warp & 3, wn = warp >> 2;          // 4x2 warp grid, 32x64 warp tile
    const int bm = blockIdx.y, bn = blockIdx.x;
    const int lr = lane >> 2, lc = lane & 3;

    int sel = 0, nb = bn;
    if (MODE == 1){ sel = bn >> 3; nb = bn & 7; }
    const float* Ag = ((MODE == 0) ? g_ao : g_x) + (size_t)bm*128*DM;
    const float* Bg = g_w + (size_t)((MODE==1)? sel : 3)*DM*DM + (size_t)nb*128*DM;

    const int r0 = tid >> 3, v0 = tid & 7;            // loader: 4 float4 chunks/matrix

    float acc[2][8][4];
    #pragma unroll
    for (int i=0;i<2;i++)
        #pragma unroll
        for (int j=0;j<8;j++)
            #pragma unroll
            for (int k=0;k<4;k++) acc[i][j][k]=0.f;

    auto load_tile = [&](int kt, int st){
        const int k0 = kt*BK;
        float* a_s = sA + st*GST;
        float* b_s = sB + st*GST;
        #pragma unroll
        for (int c=0;c<4;c++){
            int row = r0 + c*32;
            cp16(&a_s[row*SAS + v0*4], Ag + (size_t)row*DM + k0 + v0*4);
            cp16(&b_s[row*SAS + v0*4], Bg + (size_t)row*DM + k0 + v0*4);
        }
    };

    const int NT = DM/BK;   // 32
    load_tile(0, 0); cpcommit();
    load_tile(1, 1); cpcommit();

    for (int kt = 0; kt < NT; ++kt){
        const int st = kt & 1;
        if (kt < NT-1) cpwait<1>(); else cpwait<0>();
        __syncthreads();                       // stage st holds tile kt
        const float* a_s = sA + st*GST;
        const float* b_s = sB + st*GST;

        #pragma unroll
        for (int kk=0; kk<4; ++kk){
            const int ko = kk*8;
            unsigned af[2][4], bf[8][2];
            #pragma unroll
            for (int mt=0; mt<2; ++mt){
                int r = wm*32 + mt*16 + lr;
                float2 a0 = *(const float2*)&a_s[ r   *SAS + ko + 2*lc];
                float2 a1 = *(const float2*)&a_s[(r+8)*SAS + ko + 2*lc];
                af[mt][0] = __float_as_uint(a0.x);
                af[mt][1] = __float_as_uint(a1.x);
                af[mt][2] = __float_as_uint(a0.y);
                af[mt][3] = __float_as_uint(a1.y);
            }
            #pragma unroll
            for (int nf=0; nf<8; ++nf){
                int nr = wn*64 + nf*8 + lr;
                float2 b0 = *(const float2*)&b_s[nr*SAS + ko + 2*lc];
                bf[nf][0] = __float_as_uint(b0.x);
                bf[nf][1] = __float_as_uint(b0.y);
            }
            #pragma unroll
            for (int mt=0; mt<2; ++mt)
                #pragma unroll
                for (int nf=0; nf<8; ++nf)
                    mma_tf32(acc[mt][nf], af[mt], bf[nf]);
        }
        __syncthreads();                       // all warps done reading stage st
        if (kt+2 < NT){ load_tile(kt+2, st); cpcommit(); }
    }

    // ---- epilogue (C-frag layout independent of k-remap) ----
    #pragma unroll
    for (int mt=0; mt<2; ++mt){
        const int row = bm*128 + wm*32 + mt*16 + lr;
        #pragma unroll
        for (int nf=0; nf<8; ++nf){
            float c0 = acc[mt][nf][0], c1 = acc[mt][nf][1];
            float c2 = acc[mt][nf][2], c3 = acc[mt][nf][3];
            const int jl = nb*128 + wn*64 + nf*8 + 2*lc;   // column within matrix
            if (MODE == 0){
                C[(size_t)row*DM + jl]       = c0;
                C[(size_t)row*DM + jl + 1]   = c1;
                C[(size_t)(row+8)*DM + jl]   = c2;
                C[(size_t)(row+8)*DM + jl+1] = c3;
            } else {
                const int h = jl >> 6, d = jl & 63;
                const int b = row >> 11, s = row & (SEQ-1);
                if (sel < 2){
                    float* dst = (sel==0) ? g_q : g_k;
                    const size_t base = ((size_t)(b*NH + h)*SEQ + s)*HD + d;
                    const int ti  = s*(HD/2) + (d>>1);
                    const int ti2 = ti + 8*(HD/2);
                    float cs  = g_cos[ti],  sn  = g_sin[ti];
                    float cs2 = g_cos[ti2], sn2 = g_sin[ti2];
                    // q pre-scale: 1/sqrt(64) * log2(e)  (softmax runs in base 2)
                    const float qs = (sel==0) ? 0.125f*1.4426950408889634f : 1.0f;
                    dst[base]          = tfbits(qs*(c0*cs  - c1*sn));
                    dst[base+1]        = tfbits(qs*(c0*sn  + c1*cs));
                    dst[base+8*HD]     = tfbits(qs*(c2*cs2 - c3*sn2));
                    dst[base+8*HD+1]   = tfbits(qs*(c2*sn2 + c3*cs2));
                } else {
                    // V stored TRANSPOSED: [b][h][d][s]
                    float* dst = g_v;
                    const size_t tb = ((size_t)(b*NH + h)*HD);
                    dst[(tb + d  )*SEQ + s  ] = tfbits(c0);
                    dst[(tb + d+1)*SEQ + s  ] = tfbits(c1);
                    dst[(tb + d  )*SEQ + s+8] = tfbits(c2);
                    dst[(tb + d+1)*SEQ + s+8] = tfbits(c3);
                }
            }
        }
    }
}

// ---------------- FlashAttention v9: single barrier per KV tile -------------
// v8 interleaved QK/PV pipeline, plus: the tile loop is reordered to
// cpwait -> sync -> issue load(t+1) -> compute(t). The ONE top sync both
// publishes tile t and proves all warps finished tile t-1 (whose buffer the
// new load overwrites) — the bottom barrier is deleted (32 fewer barriers).
#define KS 72    // Q/K smem row stride: 8B-bank conflict-free LDS.64 pairs
#define VS 72    // V^T smem row stride: 8B-bank conflict-free LDS.64 pairs
#define ATTN_SMEM ((128*KS + 2*64*KS + 2*64*VS)*4)   // 110592 bytes

__global__ __launch_bounds__(128)
void attn_kernel()
{
    extern __shared__ float sm[];
    float* sQ = sm;                 // 128*KS
    float* sK = sQ + 128*KS;        // 2 stages of 64*KS
    float* sV = sK + 2*64*KS;       // 2 stages of 64*VS (transposed: row = d)

    const int tid = threadIdx.x, lane = tid & 31, warp = tid >> 5;
    const int lr = lane >> 2, lc = lane & 3;
    const int qt = blockIdx.x, bh = blockIdx.y;

    const float* qp = g_q + ((size_t)bh*SEQ + qt*128)*HD;
    const float* kp = g_k + (size_t)bh*SEQ*HD;
    const float* vp = g_v + (size_t)bh*HD*SEQ;     // transposed base

    auto load_kv = [&](int t, int buf){
        const float* kt_ = kp + (size_t)t*64*HD;
        const float* vt_ = vp + t*64;              // column offset in [d][s]
        #pragma unroll
        for (int c=0;c<8;c++){                 // 64 rows x 16 float4 / 128 thr
            int ch = tid + c*128;
            int row = ch >> 4, vec = ch & 15;
            cp16(&sK[buf*64*KS + row*KS + vec*4], kt_ + row*HD + vec*4);
            cp16(&sV[buf*64*VS + row*VS + vec*4], vt_ + (size_t)row*SEQ + vec*4);
        }
    };

    load_kv(0, 0); cpcommit();

    // Q tile (128 rows) -> smem (tf32 bits, pre-scaled by log2e/sqrt(64))
    #pragma unroll
    for (int c=0;c<16;c++){
        int ch = tid + c*128;
        int row = ch >> 4, vec = ch & 15;
        *(float4*)(&sQ[row*KS + vec*4]) = *(const float4*)(qp + (size_t)row*HD + vec*4);
    }
    __syncthreads();

    // Q fragments register-resident (reused all 32 tiles; paired LDS.64)
    unsigned qa[2][8][4];
    #pragma unroll
    for (int mt=0; mt<2; ++mt){
        const int r = warp*32 + mt*16 + lr;
        #pragma unroll
        for (int ks=0; ks<8; ++ks){
            float2 q0 = *(const float2*)&sQ[ r   *KS + ks*8 + 2*lc];
            float2 q1 = *(const float2*)&sQ[(r+8)*KS + ks*8 + 2*lc];
            qa[mt][ks][0] = __float_as_uint(q0.x);
            qa[mt][ks][1] = __float_as_uint(q1.x);
            qa[mt][ks][2] = __float_as_uint(q0.y);
            qa[mt][ks][3] = __float_as_uint(q1.y);
        }
    }

    float o[2][8][4];
    #pragma unroll
    for (int mt=0; mt<2; ++mt)
        #pragma unroll
        for (int i=0;i<8;i++)
            #pragma unroll
            for (int j=0;j<4;j++) o[mt][i][j]=0.f;
    float lp[2][2];                           // per-thread partial row sums
    #pragma unroll
    for (int mt=0; mt<2; ++mt){ lp[mt][0]=0.f; lp[mt][1]=0.f; }

    for (int t=0; t<SEQ/64; ++t){
        const int buf = t & 1;
        cpwait<0>();
        __syncthreads();   // tile t visible; all warps done reading tile t-1
        if (t+1 < SEQ/64){ load_kv(t+1, buf^1); cpcommit(); }

        const float* kb = &sK[buf*64*KS];
        const float* vb = &sV[buf*64*VS];

        float sc[2][8][4];
        #pragma unroll
        for (int mt=0; mt<2; ++mt)
            #pragma unroll
            for (int i=0;i<8;i++)
                #pragma unroll
                for (int j=0;j<4;j++) sc[mt][i][j]=0.f;

        // PV for score group f: ex2 -> truncate -> row-sum -> 16 mmas.
        auto pv_group = [&](int f){
            unsigned pa[2][4];
            #pragma unroll
            for (int mt=0; mt<2; ++mt){
                unsigned u0 = __float_as_uint(ex2(sc[mt][f][0])) & 0xffffe000u;
                unsigned u1 = __float_as_uint(ex2(sc[mt][f][1])) & 0xffffe000u;
                unsigned u2 = __float_as_uint(ex2(sc[mt][f][2])) & 0xffffe000u;
                unsigned u3 = __float_as_uint(ex2(sc[mt][f][3])) & 0xffffe000u;
                lp[mt][0] += __uint_as_float(u0) + __uint_as_float(u1);
                lp[mt][1] += __uint_as_float(u2) + __uint_as_float(u3);
                pa[mt][0] = u0;  pa[mt][1] = u2;   // slot lc   -> col 2lc
                pa[mt][2] = u1;  pa[mt][3] = u3;   // slot lc+4 -> col 2lc+1
            }
            #pragma unroll
            for (int nf=0; nf<8; ++nf){
                float2 vv = *(const float2*)&vb[(nf*8+lr)*VS + f*8 + 2*lc];
                unsigned bb[2];
                bb[0] = __float_as_uint(vv.x);
                bb[1] = __float_as_uint(vv.y);
                mma_tf32(o[0][nf], pa[0], bb);
                mma_tf32(o[1][nf], pa[1], bb);
            }
        };

        // Interleaved mainloop: QK group nf, then PV of group nf-2.
        #pragma unroll
        for (int nf=0; nf<8; ++nf){
            const int krow = (nf*8 + lr)*KS;
            #pragma unroll
            for (int ks=0; ks<8; ++ks){
                float2 kv2 = *(const float2*)&kb[krow + ks*8 + 2*lc];
                unsigned bb[2];
                bb[0] = __float_as_uint(kv2.x);
                bb[1] = __float_as_uint(kv2.y);
                mma_tf32(sc[0][nf], qa[0][ks], bb);
                mma_tf32(sc[1][nf], qa[1][ks], bb);
            }
            if (nf >= 2) pv_group(nf-2);
        }
        pv_group(6);
        pv_group(7);
    }

    // epilogue: single quad-reduction of row sums, normalize, write out
    const int b = bh >> 4, h = bh & 15;
    #pragma unroll
    for (int mt=0; mt<2; ++mt){
        float sA_ = lp[mt][0], sB_ = lp[mt][1];
        sA_ += __shfl_xor_sync(0xffffffffu, sA_, 1);
        sA_ += __shfl_xor_sync(0xffffffffu, sA_, 2);
        sB_ += __shfl_xor_sync(0xffffffffu, sB_, 1);
        sB_ += __shfl_xor_sync(0xffffffffu, sB_, 2);
        const float iA = 1.f/sA_, iB = 1.f/sB_;
        const int srow = qt*128 + warp*32 + mt*16 + lr;
        float* aoA = g_ao + (size_t)(b*SEQ + srow)*DM + h*HD;
        float* aoB = aoA + 8*DM;
        #pragma unroll
        for (int nf=0; nf<8; ++nf){
            const int d = nf*8 + 2*lc;
            aoA[d]   = tfbits(o[mt][nf][0]*iA);  aoA[d+1] = tfbits(o[mt][nf][1]*iA);
            aoB[d]   = tfbits(o[mt][nf][2]*iB);  aoB[d+1] = tfbits(o[mt][nf][3]*iB);
        }
    }
}

// ---------------- launch -----------------------------------------------------
extern "C" void kernel_launch(void* const* d_in, const int* in_sizes, int n_in,
                              void* d_out, int out_size)
{
    const float4* x  = (const float4*)d_in[0];
    const float4* wq = (const float4*)d_in[1];
    const float4* wk = (const float4*)d_in[2];
    const float4* wv = (const float4*)d_in[3];
    const float4* wo = (const float4*)d_in[4];
    float* out = (float*)d_out;

    static int attr_done = 0;
    if (!attr_done){
        cudaFuncSetAttribute(gemm_kernel<1>, cudaFuncAttributeMaxDynamicSharedMemorySize, GSMEM);
        cudaFuncSetAttribute(gemm_kernel<0>, cudaFuncAttributeMaxDynamicSharedMemorySize, GSMEM);
        cudaFuncSetAttribute(attn_kernel,    cudaFuncAttributeMaxDynamicSharedMemorySize, ATTN_SMEM);
        attr_done = 1;
    }

    // pre-convert x and all weights to tf32 bit-patterns
    cvt_inputs_kernel<<<(ROWS*DM/4 + 4*DM*DM/4)/256, 256>>>(x, wq, wk, wv, wo);

    rope_table_kernel<<<(SEQ*(HD/2) + 255)/256, 256>>>();

    // QKV projection + RoPE (V stored transposed):  grid = (24, 32)
    gemm_kernel<1><<<dim3(24, 32), 256, GSMEM>>>(nullptr);

    // FlashAttention: (16 q-tiles of 128 rows, 32 batch*heads)
    attn_kernel<<<dim3(SEQ/128, BATCH*NH), 128, ATTN_SMEM>>>();

    // Output projection: grid = (8 n-tiles, 32 m-tiles)
    gemm_kernel<0><<<dim3(8, 32), 256, GSMEM>>>(out);
}